// round 1
// baseline (speedup 1.0000x reference)
#include <cuda_runtime.h>
#include <cstdint>

#define BB 16
#define HH 64
#define WW 64
#define CC 512
#define RR 256
#define NREG 64
#define PH 7
#define PW 7

// Scratch for clipped ROIs passed from NMS kernel to pooling kernel.
__device__ int g_rois[BB * NREG * 4];

__device__ __forceinline__ void fix_axis(int& mn, int& mx, int ps, int fs) {
    int pad = ps - (mx - mn);
    if (pad > 0) {
        // pad > 0 here, so C truncating division == Python floor division.
        if (mn < pad / 2) {
            mn = 0; mx = ps;
        } else if (fs - mx < (1 + pad) / 2) {
            mn = fs - ps; mx = fs;
        } else {
            mn = mn - pad / 2;
            mx = mx + (1 + pad) / 2;
        }
    }
}

__global__ void nms_clip_kernel(const float* __restrict__ roi,
                                float* __restrict__ out_tail,
                                int write_tail) {
    const int b = blockIdx.x;   // batch
    const int t = threadIdx.x;  // 0..255, one ROI per thread

    __shared__ float sx1[RR], sy1[RR], sx2[RR], sy2[RR], sar[RR];
    __shared__ unsigned int ov[RR][8];  // 256-bit overlap row per ROI
    __shared__ int idx[NREG];

    const float* rp = roi + ((size_t)b * RR + t) * 4;
    const float x = rp[0], y = rp[1], w = rp[2], h = rp[3];
    const float x1 = x, y1 = y;
    const float x2 = __fadd_rn(x, w);
    const float y2 = __fadd_rn(y, h);
    sx1[t] = x1; sy1[t] = y1; sx2[t] = x2; sy2[t] = y2;
    sar[t] = __fmul_rn(__fsub_rn(y2, y1), __fsub_rn(x2, x1));
    __syncthreads();

    const float area_t = sar[t];
#pragma unroll
    for (int wd = 0; wd < 8; wd++) {
        unsigned int bits = 0;
        for (int k = 0; k < 32; k++) {
            const int j = wd * 32 + k;
            float ih = fmaxf(__fsub_rn(fminf(y2, sy2[j]), fmaxf(y1, sy1[j])), 0.0f);
            float iw = fmaxf(__fsub_rn(fminf(x2, sx2[j]), fmaxf(x1, sx1[j])), 0.0f);
            float inter = __fmul_rn(ih, iw);
            float uni = __fsub_rn(__fadd_rn(area_t, sar[j]), inter);
            float iou = (uni > 0.0f) ? __fdiv_rn(inter, uni) : 0.0f;
            if (iou > 0.4f) bits |= (1u << k);
        }
        ov[t][wd] = bits;
    }
    __syncthreads();

    // Sequential greedy scan (inherent dependency chain) by thread 0.
    if (t == 0) {
        unsigned int km[8] = {0, 0, 0, 0, 0, 0, 0, 0};
        int cnt = 0;
        for (int i = 0; i < RR; i++) {
            unsigned int s = 0;
#pragma unroll
            for (int wd = 0; wd < 8; wd++) s |= (ov[i][wd] & km[wd]);
            if (s == 0u) {
                km[i >> 5] |= (1u << (i & 31));
                if (cnt < NREG) idx[cnt] = i;
                cnt++;
            }
        }
        int filled = cnt < NREG ? cnt : NREG;
        for (int k = filled; k < NREG; k++) idx[k] = (RR - NREG) + k;  // 192+k
    }
    __syncthreads();

    // Clip the 64 selected ROIs and publish to scratch (+ output tail).
    if (t < NREG) {
        const float* rr = roi + ((size_t)b * RR + idx[t]) * 4;
        const float xf = rr[0], yf = rr[1], wf = rr[2], hf = rr[3];
        int xmin = (int)fmaxf(0.0f, xf);
        int ymin = (int)fmaxf(0.0f, yf);
        int xmax = (int)fminf((float)WW, __fadd_rn(xf, wf));
        int ymax = (int)fminf((float)HH, __fadd_rn(yf, hf));
        fix_axis(xmin, xmax, PW, WW);
        fix_axis(ymin, ymax, PH, HH);
        int* g = g_rois + ((size_t)b * NREG + t) * 4;
        g[0] = xmin; g[1] = ymin; g[2] = xmax - xmin; g[3] = ymax - ymin;
        if (write_tail) {
            float* o = out_tail + ((size_t)b * NREG + t) * 4;
            o[0] = (float)xmin;
            o[1] = (float)ymin;
            o[2] = (float)(xmax - xmin);
            o[3] = (float)(ymax - ymin);
        }
    }
}

__device__ __forceinline__ float4 max4(float4 a, float4 b) {
    float4 r;
    r.x = fmaxf(a.x, b.x);
    r.y = fmaxf(a.y, b.y);
    r.z = fmaxf(a.z, b.z);
    r.w = fmaxf(a.w, b.w);
    return r;
}

// One CTA per (batch, region). 128 threads, thread = one float4 channel group.
// All loads/stores are 2KB fully-coalesced lines across the CTA.
__global__ void __launch_bounds__(128) pool_kernel(const float* __restrict__ feat,
                                                   float* __restrict__ out) {
    const int blk = blockIdx.x;           // 0..1023
    const int b = blk >> 6;
    const int c4 = threadIdx.x;           // channel group, 0..127

    const int* g = g_rois + (size_t)blk * 4;
    const int x = g[0], y = g[1], w = g[2], h = g[3];

    const float4* fm = reinterpret_cast<const float4*>(feat) +
                       (size_t)b * HH * WW * (CC / 4) + c4;
    float4* o = reinterpret_cast<float4*>(out) + (size_t)blk * PH * PW * (CC / 4) + c4;

    auto F = [&](int row, int col) -> float4 {
        return __ldg(&fm[((size_t)row * WW + col) * (CC / 4)]);
    };

    // Rows y..y+5: direct 6x6 block copy + column-strip max (cols x+6..x+w-1).
#pragma unroll
    for (int i = 0; i < PH - 1; i++) {
        const int row = y + i;
        float4 cm = F(row, x + 6);
#pragma unroll 4
        for (int col = x + 7; col < x + w; col++) cm = max4(cm, F(row, col));
        o[((size_t)i * PW + 6) * (CC / 4)] = cm;
#pragma unroll
        for (int j = 0; j < PW - 1; j++) {
            o[((size_t)i * PW + j) * (CC / 4)] = F(row, x + j);
        }
    }

    // Rows y+6..y+h-1: row-strip max (cols x..x+5) + corner max (cols x+6..x+w-1).
    float4 rs[PW - 1];
    float4 corner;
    {
        const int row = y + 6;  // h >= 7 guaranteed after clipping
#pragma unroll
        for (int j = 0; j < PW - 1; j++) rs[j] = F(row, x + j);
        corner = F(row, x + 6);
#pragma unroll 4
        for (int col = x + 7; col < x + w; col++) corner = max4(corner, F(row, col));
    }
    for (int row = y + 7; row < y + h; row++) {
        float4 cm = F(row, x + 6);
#pragma unroll 4
        for (int col = x + 7; col < x + w; col++) cm = max4(cm, F(row, col));
        corner = max4(corner, cm);
#pragma unroll
        for (int j = 0; j < PW - 1; j++) rs[j] = max4(rs[j], F(row, x + j));
    }

#pragma unroll
    for (int j = 0; j < PW - 1; j++) {
        o[((size_t)(PH - 1) * PW + j) * (CC / 4)] = rs[j];
    }
    o[(size_t)(PH * PW - 1) * (CC / 4)] = corner;
}

extern "C" void kernel_launch(void* const* d_in, const int* in_sizes, int n_in,
                              void* d_out, int out_size) {
    // metadata order: features (B*H*W*C), roi (B*R*4). Disambiguate by size.
    const float* features = (const float*)d_in[0];
    const float* roi = (const float*)d_in[1];
    if (n_in >= 2 && in_sizes[0] == BB * RR * 4) {
        roi = (const float*)d_in[0];
        features = (const float*)d_in[1];
    }

    const long long pooled_elems = (long long)BB * NREG * PH * PW * CC;  // 25,690,112
    float* out = (float*)d_out;
    int write_tail = (out_size > pooled_elems) ? 1 : 0;
    float* tail = out + pooled_elems;

    nms_clip_kernel<<<BB, RR>>>(roi, tail, write_tail);
    pool_kernel<<<BB * NREG, 128>>>(features, out);
}

// round 2
// speedup vs baseline: 1.2715x; 1.2715x over previous
#include <cuda_runtime.h>
#include <cstdint>

#define BB 16
#define HH 64
#define WW 64
#define CC 512
#define RR 256
#define NREG 64
#define PH 7
#define PW 7
#define CSPLIT 4   // CTAs per region (channel split)

// Scratch for clipped ROIs passed from NMS kernel to pooling kernel.
__device__ int g_rois[BB * NREG * 4];

__device__ __forceinline__ void fix_axis(int& mn, int& mx, int ps, int fs) {
    int pad = ps - (mx - mn);
    if (pad > 0) {
        if (mn < pad / 2) {
            mn = 0; mx = ps;
        } else if (fs - mx < (1 + pad) / 2) {
            mn = fs - ps; mx = fs;
        } else {
            mn = mn - pad / 2;
            mx = mx + (1 + pad) / 2;
        }
    }
}

__global__ void nms_clip_kernel(const float* __restrict__ roi,
                                float* __restrict__ out_tail,
                                int write_tail) {
    const int b = blockIdx.x;   // batch
    const int t = threadIdx.x;  // 0..255, one ROI per thread

    __shared__ float sx1[RR], sy1[RR], sx2[RR], sy2[RR], sar[RR];
    __shared__ __align__(16) unsigned int ov[RR][8];  // 256-bit overlap row per ROI
    __shared__ int idx[NREG];

    const float* rp = roi + ((size_t)b * RR + t) * 4;
    const float x = rp[0], y = rp[1], w = rp[2], h = rp[3];
    const float x1 = x, y1 = y;
    const float x2 = __fadd_rn(x, w);
    const float y2 = __fadd_rn(y, h);
    sx1[t] = x1; sy1[t] = y1; sx2[t] = x2; sy2[t] = y2;
    sar[t] = __fmul_rn(__fsub_rn(y2, y1), __fsub_rn(x2, x1));
    __syncthreads();

    const float area_t = sar[t];
#pragma unroll
    for (int wd = 0; wd < 8; wd++) {
        unsigned int bits = 0;
        for (int k = 0; k < 32; k++) {
            const int j = wd * 32 + k;
            float ih = fmaxf(__fsub_rn(fminf(y2, sy2[j]), fmaxf(y1, sy1[j])), 0.0f);
            float iw = fmaxf(__fsub_rn(fminf(x2, sx2[j]), fmaxf(x1, sx1[j])), 0.0f);
            float inter = __fmul_rn(ih, iw);
            float uni = __fsub_rn(__fadd_rn(area_t, sar[j]), inter);
            float iou = (uni > 0.0f) ? __fdiv_rn(inter, uni) : 0.0f;
            if (iou > 0.4f) bits |= (1u << k);
        }
        ov[t][wd] = bits;
    }
    __syncthreads();

    // Sequential greedy scan (inherent dependency chain) by thread 0.
    // uint4 loads cut the per-iteration shared-load count from 8 to 2.
    if (t == 0) {
        uint4 km0 = make_uint4(0, 0, 0, 0);
        uint4 km1 = make_uint4(0, 0, 0, 0);
        int cnt = 0;
        const uint4* ovv = reinterpret_cast<const uint4*>(&ov[0][0]);
        for (int i = 0; i < RR; i++) {
            uint4 r0 = ovv[i * 2 + 0];
            uint4 r1 = ovv[i * 2 + 1];
            unsigned int s = (r0.x & km0.x) | (r0.y & km0.y) | (r0.z & km0.z) | (r0.w & km0.w)
                           | (r1.x & km1.x) | (r1.y & km1.y) | (r1.z & km1.z) | (r1.w & km1.w);
            if (s == 0u) {
                unsigned int bit = 1u << (i & 31);
                switch (i >> 5) {
                    case 0: km0.x |= bit; break;
                    case 1: km0.y |= bit; break;
                    case 2: km0.z |= bit; break;
                    case 3: km0.w |= bit; break;
                    case 4: km1.x |= bit; break;
                    case 5: km1.y |= bit; break;
                    case 6: km1.z |= bit; break;
                    default: km1.w |= bit; break;
                }
                if (cnt < NREG) idx[cnt] = i;
                cnt++;
            }
        }
        int filled = cnt < NREG ? cnt : NREG;
        for (int k = filled; k < NREG; k++) idx[k] = (RR - NREG) + k;  // 192+k
    }
    __syncthreads();

    // Clip the 64 selected ROIs and publish to scratch (+ output tail).
    if (t < NREG) {
        const float* rr = roi + ((size_t)b * RR + idx[t]) * 4;
        const float xf = rr[0], yf = rr[1], wf = rr[2], hf = rr[3];
        int xmin = (int)fmaxf(0.0f, xf);
        int ymin = (int)fmaxf(0.0f, yf);
        int xmax = (int)fminf((float)WW, __fadd_rn(xf, wf));
        int ymax = (int)fminf((float)HH, __fadd_rn(yf, hf));
        fix_axis(xmin, xmax, PW, WW);
        fix_axis(ymin, ymax, PH, HH);
        int* g = g_rois + ((size_t)b * NREG + t) * 4;
        g[0] = xmin; g[1] = ymin; g[2] = xmax - xmin; g[3] = ymax - ymin;
        if (write_tail) {
            float* o = out_tail + ((size_t)b * NREG + t) * 4;
            o[0] = (float)xmin;
            o[1] = (float)ymin;
            o[2] = (float)(xmax - xmin);
            o[3] = (float)(ymax - ymin);
        }
    }
}

__device__ __forceinline__ float4 max4(float4 a, float4 b) {
    float4 r;
    r.x = fmaxf(a.x, b.x);
    r.y = fmaxf(a.y, b.y);
    r.z = fmaxf(a.z, b.z);
    r.w = fmaxf(a.w, b.w);
    return r;
}

// CSPLIT one-warp CTAs per (batch, region); each warp owns 32 float4 channel
// groups. Loads/stores are 512B fully-coalesced lines per warp; every feature
// element in the window is read exactly once per region.
__global__ void __launch_bounds__(32) pool_kernel(const float* __restrict__ feat,
                                                  float* __restrict__ out) {
    const int blk = blockIdx.x;            // 0 .. BB*NREG*CSPLIT-1
    const int reg = blk >> 2;              // region index (b*NREG + r)
    const int q = blk & (CSPLIT - 1);      // channel quarter
    const int b = reg >> 6;
    const int c4 = q * 32 + threadIdx.x;   // float4 channel group, 0..127

    const int* g = g_rois + (size_t)reg * 4;
    const int x = g[0], y = g[1], w = g[2], h = g[3];

    const float4* fm = reinterpret_cast<const float4*>(feat) +
                       (size_t)b * HH * WW * (CC / 4) + c4;
    float4* o = reinterpret_cast<float4*>(out) + (size_t)reg * PH * PW * (CC / 4) + c4;

    auto F = [&](int row, int col) -> float4 {
        return __ldg(&fm[((size_t)row * WW + col) * (CC / 4)]);
    };

    // Rows y..y+5: direct 6x6 block copy + column-strip max (cols x+6..x+w-1).
#pragma unroll
    for (int i = 0; i < PH - 1; i++) {
        const int row = y + i;
        float4 cm = F(row, x + 6);
#pragma unroll 4
        for (int col = x + 7; col < x + w; col++) cm = max4(cm, F(row, col));
        o[((size_t)i * PW + 6) * (CC / 4)] = cm;
#pragma unroll
        for (int j = 0; j < PW - 1; j++) {
            o[((size_t)i * PW + j) * (CC / 4)] = F(row, x + j);
        }
    }

    // Rows y+6..y+h-1: row-strip max (cols x..x+5) + corner max (cols x+6..x+w-1).
    float4 rs[PW - 1];
    float4 corner;
    {
        const int row = y + 6;  // h >= 7 guaranteed after clipping
#pragma unroll
        for (int j = 0; j < PW - 1; j++) rs[j] = F(row, x + j);
        corner = F(row, x + 6);
#pragma unroll 4
        for (int col = x + 7; col < x + w; col++) corner = max4(corner, F(row, col));
    }
    for (int row = y + 7; row < y + h; row++) {
        float4 cm = F(row, x + 6);
#pragma unroll 4
        for (int col = x + 7; col < x + w; col++) cm = max4(cm, F(row, col));
        corner = max4(corner, cm);
#pragma unroll
        for (int j = 0; j < PW - 1; j++) rs[j] = max4(rs[j], F(row, x + j));
    }

#pragma unroll
    for (int j = 0; j < PW - 1; j++) {
        o[((size_t)(PH - 1) * PW + j) * (CC / 4)] = rs[j];
    }
    o[(size_t)(PH * PW - 1) * (CC / 4)] = corner;
}

extern "C" void kernel_launch(void* const* d_in, const int* in_sizes, int n_in,
                              void* d_out, int out_size) {
    // metadata order: features (B*H*W*C), roi (B*R*4). Disambiguate by size.
    const float* features = (const float*)d_in[0];
    const float* roi = (const float*)d_in[1];
    if (n_in >= 2 && in_sizes[0] == BB * RR * 4) {
        roi = (const float*)d_in[0];
        features = (const float*)d_in[1];
    }

    const long long pooled_elems = (long long)BB * NREG * PH * PW * CC;  // 25,690,112
    float* out = (float*)d_out;
    int write_tail = (out_size > pooled_elems) ? 1 : 0;
    float* tail = out + pooled_elems;

    nms_clip_kernel<<<BB, RR>>>(roi, tail, write_tail);
    pool_kernel<<<BB * NREG * CSPLIT, 32>>>(features, out);
}

// round 5
// speedup vs baseline: 2.6546x; 2.0878x over previous
#include <cuda_runtime.h>
#include <cstdint>

#define BB 16
#define HH 64
#define WW 64
#define CC 512
#define RR 256
#define NREG 64
#define PH 7
#define PW 7

#define NEGINF __int_as_float(0xff800000)

// Scratch for clipped ROIs passed from NMS kernel to pooling kernel.
__device__ int g_rois[BB * NREG * 4];

__device__ __forceinline__ void fix_axis(int& mn, int& mx, int ps, int fs) {
    int pad = ps - (mx - mn);
    if (pad > 0) {
        if (mn < pad / 2) {
            mn = 0; mx = ps;
        } else if (fs - mx < (1 + pad) / 2) {
            mn = fs - ps; mx = fs;
        } else {
            mn = mn - pad / 2;
            mx = mx + (1 + pad) / 2;
        }
    }
}

__global__ void nms_clip_kernel(const float* __restrict__ roi,
                                float* __restrict__ out_tail,
                                int write_tail) {
    const int b = blockIdx.x;   // batch
    const int t = threadIdx.x;  // 0..255, one ROI per thread

    __shared__ float sx1[RR], sy1[RR], sx2[RR], sy2[RR], sar[RR];
    __shared__ unsigned int ov[8][RR];   // transposed: ov[word][roi]
    __shared__ int idx[NREG];

    const float* rp = roi + ((size_t)b * RR + t) * 4;
    const float x = rp[0], y = rp[1], w = rp[2], h = rp[3];
    const float x1 = x, y1 = y;
    const float x2 = __fadd_rn(x, w);
    const float y2 = __fadd_rn(y, h);
    sx1[t] = x1; sy1[t] = y1; sx2[t] = x2; sy2[t] = y2;
    sar[t] = __fmul_rn(__fsub_rn(y2, y1), __fsub_rn(x2, x1));
    __syncthreads();

    const float area_t = sar[t];
#pragma unroll
    for (int wd = 0; wd < 8; wd++) {
        unsigned int bits = 0;
        for (int k = 0; k < 32; k++) {
            const int j = wd * 32 + k;
            float ih = fmaxf(__fsub_rn(fminf(y2, sy2[j]), fmaxf(y1, sy1[j])), 0.0f);
            float iw = fmaxf(__fsub_rn(fminf(x2, sx2[j]), fmaxf(x1, sx1[j])), 0.0f);
            float inter = __fmul_rn(ih, iw);
            float uni = __fsub_rn(__fadd_rn(area_t, sar[j]), inter);
            float iou = (uni > 0.0f) ? __fdiv_rn(inter, uni) : 0.0f;
            if (iou > 0.4f) bits |= (1u << k);
        }
        ov[wd][t] = bits;
    }
    __syncthreads();

    // Block-parallel greedy scan by warp 0: 32 candidates per step.
    if (t < 32) {
        const int lane = t;
        unsigned int km[8] = {0, 0, 0, 0, 0, 0, 0, 0};  // kept mask (replicated per lane)
        int cnt = 0;                                     // replicated per lane
#pragma unroll
        for (int bb = 0; bb < 8; bb++) {
            const int i = bb * 32 + lane;
            // Conflict with kept ROIs from earlier blocks (parallel across lanes).
            unsigned int s = 0;
#pragma unroll
            for (int wd = 0; wd < 8; wd++) s |= (ov[wd][i] & km[wd]);
            unsigned int candmask = __ballot_sync(0xffffffffu, s == 0u);
            unsigned int myrow = ov[bb][i];  // in-block conflict word for candidate i
            // In-block greedy resolution (identical on every lane, pure ALU).
            unsigned int kept = 0;
#pragma unroll 8
            for (int k = 0; k < 32; k++) {
                unsigned int rk = __shfl_sync(0xffffffffu, myrow, k);
                if ((candmask >> k) & 1u) {
                    if (!(rk & kept)) kept |= (1u << k);
                }
            }
            // Record kept indices in rank order.
            if ((kept >> lane) & 1u) {
                int rank = cnt + __popc(kept & ((1u << lane) - 1u));
                if (rank < NREG) idx[rank] = i;
            }
            km[bb] = kept;
            cnt += __popc(kept);
        }
        // Fill remaining slots: idx[k] = 192 + k.
        for (int k = cnt + lane; k < NREG; k += 32) idx[k] = (RR - NREG) + k;
    }
    __syncthreads();

    // Clip the 64 selected ROIs and publish to scratch (+ output tail).
    if (t < NREG) {
        const float* rr = roi + ((size_t)b * RR + idx[t]) * 4;
        const float xf = rr[0], yf = rr[1], wf = rr[2], hf = rr[3];
        int xmin = (int)fmaxf(0.0f, xf);
        int ymin = (int)fmaxf(0.0f, yf);
        int xmax = (int)fminf((float)WW, __fadd_rn(xf, wf));
        int ymax = (int)fminf((float)HH, __fadd_rn(yf, hf));
        fix_axis(xmin, xmax, PW, WW);
        fix_axis(ymin, ymax, PH, HH);
        int* g = g_rois + ((size_t)b * NREG + t) * 4;
        g[0] = xmin; g[1] = ymin; g[2] = xmax - xmin; g[3] = ymax - ymin;
        if (write_tail) {
            float* o = out_tail + ((size_t)b * NREG + t) * 4;
            o[0] = (float)xmin;
            o[1] = (float)ymin;
            o[2] = (float)(xmax - xmin);
            o[3] = (float)(ymax - ymin);
        }
    }
}

__device__ __forceinline__ float4 max4(float4 a, float4 b) {
    float4 r;
    r.x = fmaxf(a.x, b.x);
    r.y = fmaxf(a.y, b.y);
    r.z = fmaxf(a.z, b.z);
    r.w = fmaxf(a.w, b.w);
    return r;
}

// CTA = (region, channel quarter); 4 warps split the window ROWS, then a
// shared-memory max-reduce combines row-strip / corner partials. Per-CTA
// serial length is ~4x shorter than the one-warp version -> better balance.
__global__ void __launch_bounds__(128) pool_kernel(const float* __restrict__ feat,
                                                   float* __restrict__ out) {
    const int reg = blockIdx.x;            // b*NREG + r, 0..1023
    const int q = blockIdx.y;              // channel quarter, 0..3
    const int lane = threadIdx.x & 31;
    const int wrp = threadIdx.x >> 5;      // row-chunk warp, 0..3
    const int b = reg >> 6;
    const int c4 = q * 32 + lane;          // float4 channel group, 0..127

    const int* g = g_rois + (size_t)reg * 4;
    const int x = g[0], y = g[1], w = g[2], h = g[3];

    const float4* fm = reinterpret_cast<const float4*>(feat) +
                       (size_t)b * HH * WW * (CC / 4) + c4;
    float4* o = reinterpret_cast<float4*>(out) + (size_t)reg * PH * PW * (CC / 4) + c4;

    auto F = [&](int row, int col) -> float4 {
        return __ldg(&fm[((size_t)row * WW + col) * (CC / 4)]);
    };

    const float4 NI4 = make_float4(NEGINF, NEGINF, NEGINF, NEGINF);

    // Top 6 rows, round-robin over warps: 6-col block copy + column-strip max.
    for (int i = wrp; i < PH - 1; i += 4) {
        const int row = y + i;
#pragma unroll
        for (int j = 0; j < PW - 1; j++) {
            o[((size_t)i * PW + j) * (CC / 4)] = F(row, x + j);
        }
        float4 a0 = F(row, x + 6);
        float4 a1 = NI4;
        int col = x + 7;
        for (; col + 1 < x + w; col += 2) {
            a0 = max4(a0, F(row, col));
            a1 = max4(a1, F(row, col + 1));
        }
        if (col < x + w) a0 = max4(a0, F(row, col));
        o[((size_t)i * PW + 6) * (CC / 4)] = max4(a0, a1);
    }

    // Bottom rows y+6..y+h-1, strided over warps: partial row-strip + corner.
    float4 rs[PW - 1];
#pragma unroll
    for (int j = 0; j < PW - 1; j++) rs[j] = NI4;
    float4 c0 = NI4, c1 = NI4;
    for (int row = y + 6 + wrp; row < y + h; row += 4) {
#pragma unroll
        for (int j = 0; j < PW - 1; j++) rs[j] = max4(rs[j], F(row, x + j));
        int col = x + 6;
        for (; col + 1 < x + w; col += 2) {
            c0 = max4(c0, F(row, col));
            c1 = max4(c1, F(row, col + 1));
        }
        if (col < x + w) c0 = max4(c0, F(row, col));
    }
    float4 corner = max4(c0, c1);

    // Cross-warp reduce via shared memory: 7 outputs (rs[0..5], corner).
    __shared__ float4 part[4][PW][32];
#pragma unroll
    for (int j = 0; j < PW - 1; j++) part[wrp][j][lane] = rs[j];
    part[wrp][6][lane] = corner;
    __syncthreads();

    for (int j = wrp; j < PW; j += 4) {
        float4 m = max4(max4(part[0][j][lane], part[1][j][lane]),
                        max4(part[2][j][lane], part[3][j][lane]));
        // outputs for pooled row 6: indices 42+j (j=6 -> corner at 48)
        o[(size_t)(42 + j) * (CC / 4)] = m;
    }
}

extern "C" void kernel_launch(void* const* d_in, const int* in_sizes, int n_in,
                              void* d_out, int out_size) {
    // metadata order: features (B*H*W*C), roi (B*R*4). Disambiguate by size.
    const float* features = (const float*)d_in[0];
    const float* roi = (const float*)d_in[1];
    if (n_in >= 2 && in_sizes[0] == BB * RR * 4) {
        roi = (const float*)d_in[0];
        features = (const float*)d_in[1];
    }

    const long long pooled_elems = (long long)BB * NREG * PH * PW * CC;  // 25,690,112
    float* out = (float*)d_out;
    int write_tail = (out_size > pooled_elems) ? 1 : 0;
    float* tail = out + pooled_elems;

    nms_clip_kernel<<<BB, RR>>>(roi, tail, write_tail);
    pool_kernel<<<dim3(BB * NREG, 4, 1), 128>>>(features, out);
}

// round 6
// speedup vs baseline: 3.7130x; 1.3987x over previous
#include <cuda_runtime.h>
#include <cstdint>

#define BB 16
#define HH 64
#define WW 64
#define CC 512
#define RR 256
#define NREG 64
#define PH 7
#define PW 7

#define NEGINF __int_as_float(0xff800000)

// Scratch for clipped ROIs passed from NMS kernel to pooling kernel.
__device__ int g_rois[BB * NREG * 4];

__device__ __forceinline__ void fix_axis(int& mn, int& mx, int ps, int fs) {
    int pad = ps - (mx - mn);
    if (pad > 0) {
        if (mn < pad / 2) {
            mn = 0; mx = ps;
        } else if (fs - mx < (1 + pad) / 2) {
            mn = fs - ps; mx = fs;
        } else {
            mn = mn - pad / 2;
            mx = mx + (1 + pad) / 2;
        }
    }
}

// 1024 threads: thread = (roi t, j-segment). IoU matrix built with 4x the
// parallelism of the previous version; greedy scan stays warp-parallel.
__global__ void __launch_bounds__(1024) nms_clip_kernel(const float* __restrict__ roi,
                                                        float* __restrict__ out_tail,
                                                        int write_tail) {
    const int b = blockIdx.x;       // batch
    const int tid = threadIdx.x;    // 0..1023
    const int t = tid & 255;        // roi index
    const int seg = tid >> 8;       // j-segment, 0..3 (2 words of 32 each)

    __shared__ float sx1[RR], sy1[RR], sx2[RR], sy2[RR], sar[RR];
    __shared__ unsigned int ov[8][RR];   // transposed: ov[word][roi]
    __shared__ int idx[NREG];

    if (seg == 0) {
        float4 r4 = reinterpret_cast<const float4*>(roi)[(size_t)b * RR + t];
        float x2v = __fadd_rn(r4.x, r4.z);
        float y2v = __fadd_rn(r4.y, r4.w);
        sx1[t] = r4.x; sy1[t] = r4.y; sx2[t] = x2v; sy2[t] = y2v;
        sar[t] = __fmul_rn(__fsub_rn(y2v, r4.y), __fsub_rn(x2v, r4.x));
    }
    __syncthreads();

    const float x1 = sx1[t], y1 = sy1[t], x2 = sx2[t], y2 = sy2[t];
    const float area_t = sar[t];
#pragma unroll
    for (int wi = 0; wi < 2; wi++) {
        const int wd = seg * 2 + wi;
        unsigned int bits = 0;
        for (int k = 0; k < 32; k++) {
            const int j = wd * 32 + k;
            float ih = fmaxf(__fsub_rn(fminf(y2, sy2[j]), fmaxf(y1, sy1[j])), 0.0f);
            float iw = fmaxf(__fsub_rn(fminf(x2, sx2[j]), fmaxf(x1, sx1[j])), 0.0f);
            float inter = __fmul_rn(ih, iw);
            float uni = __fsub_rn(__fadd_rn(area_t, sar[j]), inter);
            float iou = (uni > 0.0f) ? __fdiv_rn(inter, uni) : 0.0f;
            if (iou > 0.4f) bits |= (1u << k);
        }
        ov[wd][t] = bits;
    }
    __syncthreads();

    // Block-parallel greedy scan by warp 0: 32 candidates per step.
    if (tid < 32) {
        const int lane = tid;
        unsigned int km[8] = {0, 0, 0, 0, 0, 0, 0, 0};  // kept mask (replicated)
        int cnt = 0;
#pragma unroll
        for (int bb = 0; bb < 8; bb++) {
            const int i = bb * 32 + lane;
            unsigned int s = 0;
#pragma unroll
            for (int wd = 0; wd < 8; wd++) s |= (ov[wd][i] & km[wd]);
            unsigned int candmask = __ballot_sync(0xffffffffu, s == 0u);
            unsigned int myrow = ov[bb][i];  // in-block conflict word for candidate i
            unsigned int kept = 0;
#pragma unroll 8
            for (int k = 0; k < 32; k++) {
                unsigned int rk = __shfl_sync(0xffffffffu, myrow, k);
                if ((candmask >> k) & 1u) {
                    if (!(rk & kept)) kept |= (1u << k);
                }
            }
            if ((kept >> lane) & 1u) {
                int rank = cnt + __popc(kept & ((1u << lane) - 1u));
                if (rank < NREG) idx[rank] = i;
            }
            km[bb] = kept;
            cnt += __popc(kept);
        }
        for (int k = cnt + lane; k < NREG; k += 32) idx[k] = (RR - NREG) + k;
    }
    __syncthreads();

    // Clip the 64 selected ROIs and publish to scratch (+ output tail).
    if (tid < NREG) {
        const float* rr = roi + ((size_t)b * RR + idx[tid]) * 4;
        const float xf = rr[0], yf = rr[1], wf = rr[2], hf = rr[3];
        int xmin = (int)fmaxf(0.0f, xf);
        int ymin = (int)fmaxf(0.0f, yf);
        int xmax = (int)fminf((float)WW, __fadd_rn(xf, wf));
        int ymax = (int)fminf((float)HH, __fadd_rn(yf, hf));
        fix_axis(xmin, xmax, PW, WW);
        fix_axis(ymin, ymax, PH, HH);
        int* g = g_rois + ((size_t)b * NREG + tid) * 4;
        g[0] = xmin; g[1] = ymin; g[2] = xmax - xmin; g[3] = ymax - ymin;
        if (write_tail) {
            float* o = out_tail + ((size_t)b * NREG + tid) * 4;
            o[0] = (float)xmin;
            o[1] = (float)ymin;
            o[2] = (float)(xmax - xmin);
            o[3] = (float)(ymax - ymin);
        }
    }
}

__device__ __forceinline__ float4 max4(float4 a, float4 b) {
    float4 r;
    r.x = fmaxf(a.x, b.x);
    r.y = fmaxf(a.y, b.y);
    r.z = fmaxf(a.z, b.z);
    r.w = fmaxf(a.w, b.w);
    return r;
}

// CTA = (region, channel quarter); 4 warps split ALL window rows evenly
// (unified loop), shared-memory max-reduce combines bottom-strip partials.
// Output stores are streaming (.cs) — never re-read, keep them out of L2.
__global__ void __launch_bounds__(128) pool_kernel(const float* __restrict__ feat,
                                                   float* __restrict__ out) {
    const int reg = blockIdx.x;            // b*NREG + r, 0..1023
    const int q = blockIdx.y;              // channel quarter, 0..3
    const int lane = threadIdx.x & 31;
    const int wrp = threadIdx.x >> 5;      // row-chunk warp, 0..3
    const int b = reg >> 6;
    const int c4 = q * 32 + lane;          // float4 channel group, 0..127

    const int* g = g_rois + (size_t)reg * 4;
    const int x = g[0], y = g[1], w = g[2], h = g[3];

    const float4* fm = reinterpret_cast<const float4*>(feat) +
                       (size_t)b * HH * WW * (CC / 4) + c4;
    float4* o = reinterpret_cast<float4*>(out) + (size_t)reg * PH * PW * (CC / 4) + c4;

    auto F = [&](int row, int col) -> float4 {
        return __ldg(&fm[((size_t)row * WW + col) * (CC / 4)]);
    };

    const float4 NI4 = make_float4(NEGINF, NEGINF, NEGINF, NEGINF);

    float4 rs[PW - 1];
#pragma unroll
    for (int j = 0; j < PW - 1; j++) rs[j] = NI4;
    float4 c0 = NI4, c1 = NI4;

    // Unified row loop: rows 0..5 produce direct outputs; rows >= 6 accumulate
    // row-strip / corner partials. Each warp gets ceil((h-wrp)/4) rows.
    for (int r = wrp; r < h; r += 4) {
        const int row = y + r;
        if (r < PH - 1) {
#pragma unroll
            for (int j = 0; j < PW - 1; j++) {
                __stcs(&o[((size_t)r * PW + j) * (CC / 4)], F(row, x + j));
            }
            float4 a0 = F(row, x + 6);
            float4 a1 = NI4, a2 = NI4, a3 = NI4;
            int col = x + 7;
            for (; col + 3 < x + w; col += 4) {
                a0 = max4(a0, F(row, col));
                a1 = max4(a1, F(row, col + 1));
                a2 = max4(a2, F(row, col + 2));
                a3 = max4(a3, F(row, col + 3));
            }
            for (; col < x + w; col++) a0 = max4(a0, F(row, col));
            __stcs(&o[((size_t)r * PW + 6) * (CC / 4)],
                   max4(max4(a0, a1), max4(a2, a3)));
        } else {
#pragma unroll
            for (int j = 0; j < PW - 1; j++) rs[j] = max4(rs[j], F(row, x + j));
            int col = x + 6;
            for (; col + 1 < x + w; col += 2) {
                c0 = max4(c0, F(row, col));
                c1 = max4(c1, F(row, col + 1));
            }
            if (col < x + w) c0 = max4(c0, F(row, col));
        }
    }
    float4 corner = max4(c0, c1);

    // Cross-warp reduce via shared memory: 7 outputs (rs[0..5], corner).
    __shared__ float4 part[4][PW][32];
#pragma unroll
    for (int j = 0; j < PW - 1; j++) part[wrp][j][lane] = rs[j];
    part[wrp][6][lane] = corner;
    __syncthreads();

    for (int j = wrp; j < PW; j += 4) {
        float4 m = max4(max4(part[0][j][lane], part[1][j][lane]),
                        max4(part[2][j][lane], part[3][j][lane]));
        // outputs for pooled row 6: indices 42+j (j=6 -> corner at 48)
        __stcs(&o[(size_t)(42 + j) * (CC / 4)], m);
    }
}

extern "C" void kernel_launch(void* const* d_in, const int* in_sizes, int n_in,
                              void* d_out, int out_size) {
    // metadata order: features (B*H*W*C), roi (B*R*4). Disambiguate by size.
    const float* features = (const float*)d_in[0];
    const float* roi = (const float*)d_in[1];
    if (n_in >= 2 && in_sizes[0] == BB * RR * 4) {
        roi = (const float*)d_in[0];
        features = (const float*)d_in[1];
    }

    const long long pooled_elems = (long long)BB * NREG * PH * PW * CC;  // 25,690,112
    float* out = (float*)d_out;
    int write_tail = (out_size > pooled_elems) ? 1 : 0;
    float* tail = out + pooled_elems;

    nms_clip_kernel<<<BB, 1024>>>(roi, tail, write_tail);
    pool_kernel<<<dim3(BB * NREG, 4, 1), 128>>>(features, out);
}

// round 7
// speedup vs baseline: 3.9874x; 1.0739x over previous
#include <cuda_runtime.h>
#include <cstdint>

#define BB 16
#define HH 64
#define WW 64
#define CC 512
#define RR 256
#define NREG 64
#define PH 7
#define PW 7

#define NEGINF __int_as_float(0xff800000)

// Scratch for clipped ROIs passed from NMS kernel to pooling kernel.
__device__ int4 g_rois[BB * NREG];

__device__ __forceinline__ void fix_axis(int& mn, int& mx, int ps, int fs) {
    int pad = ps - (mx - mn);
    if (pad > 0) {
        if (mn < pad / 2) {
            mn = 0; mx = ps;
        } else if (fs - mx < (1 + pad) / 2) {
            mn = fs - ps; mx = fs;
        } else {
            mn = mn - pad / 2;
            mx = mx + (1 + pad) / 2;
        }
    }
}

// 1024 threads: thread = (roi t, j-segment). Fast divide with exact fallback
// only inside a tiny band around the 0.4 threshold (bit-identical decisions).
__global__ void __launch_bounds__(1024) nms_clip_kernel(const float* __restrict__ roi,
                                                        float* __restrict__ out_tail,
                                                        int write_tail) {
    const int b = blockIdx.x;       // batch
    const int tid = threadIdx.x;    // 0..1023
    const int t = tid & 255;        // roi index
    const int seg = tid >> 8;       // j-segment, 0..3 (2 words of 32 each)

    __shared__ float sx1[RR], sy1[RR], sx2[RR], sy2[RR], sar[RR];
    __shared__ unsigned int ov[8][RR];   // transposed: ov[word][roi]
    __shared__ int idx[NREG];

    if (seg == 0) {
        float4 r4 = reinterpret_cast<const float4*>(roi)[(size_t)b * RR + t];
        float x2v = __fadd_rn(r4.x, r4.z);
        float y2v = __fadd_rn(r4.y, r4.w);
        sx1[t] = r4.x; sy1[t] = r4.y; sx2[t] = x2v; sy2[t] = y2v;
        sar[t] = __fmul_rn(__fsub_rn(y2v, r4.y), __fsub_rn(x2v, r4.x));
    }
    __syncthreads();

    const float x1 = sx1[t], y1 = sy1[t], x2 = sx2[t], y2 = sy2[t];
    const float area_t = sar[t];
#pragma unroll
    for (int wi = 0; wi < 2; wi++) {
        const int wd = seg * 2 + wi;
        unsigned int bits = 0;
        for (int k = 0; k < 32; k++) {
            const int j = wd * 32 + k;
            float ih = fmaxf(__fsub_rn(fminf(y2, sy2[j]), fmaxf(y1, sy1[j])), 0.0f);
            float iw = fmaxf(__fsub_rn(fminf(x2, sx2[j]), fmaxf(x1, sx1[j])), 0.0f);
            float inter = __fmul_rn(ih, iw);
            float uni = __fsub_rn(__fadd_rn(area_t, sar[j]), inter);
            bool dec = false;
            if (uni > 0.0f) {
                float r = __fdividef(inter, uni);   // ~2 ulp fast path
                if (r > 0.4f + 1e-5f) dec = true;
                else if (r >= 0.4f - 1e-5f)          // ambiguous band: exact
                    dec = __fdiv_rn(inter, uni) > 0.4f;
            }
            if (dec) bits |= (1u << k);
        }
        ov[wd][t] = bits;
    }
    __syncthreads();

    // Block-parallel greedy scan by warp 0: 32 candidates per step.
    if (tid < 32) {
        const int lane = tid;
        unsigned int km[8] = {0, 0, 0, 0, 0, 0, 0, 0};  // kept mask (replicated)
        int cnt = 0;
#pragma unroll
        for (int bb = 0; bb < 8; bb++) {
            const int i = bb * 32 + lane;
            unsigned int s = 0;
#pragma unroll
            for (int wd = 0; wd < 8; wd++) s |= (ov[wd][i] & km[wd]);
            unsigned int candmask = __ballot_sync(0xffffffffu, s == 0u);
            unsigned int myrow = ov[bb][i];  // in-block conflict word for candidate i
            unsigned int kept = 0;
#pragma unroll 8
            for (int k = 0; k < 32; k++) {
                unsigned int rk = __shfl_sync(0xffffffffu, myrow, k);
                if ((candmask >> k) & 1u) {
                    if (!(rk & kept)) kept |= (1u << k);
                }
            }
            if ((kept >> lane) & 1u) {
                int rank = cnt + __popc(kept & ((1u << lane) - 1u));
                if (rank < NREG) idx[rank] = i;
            }
            km[bb] = kept;
            cnt += __popc(kept);
        }
        for (int k = cnt + lane; k < NREG; k += 32) idx[k] = (RR - NREG) + k;
    }
    __syncthreads();

    // Clip the 64 selected ROIs and publish to scratch (+ output tail).
    if (tid < NREG) {
        const float* rr = roi + ((size_t)b * RR + idx[tid]) * 4;
        const float xf = rr[0], yf = rr[1], wf = rr[2], hf = rr[3];
        int xmin = (int)fmaxf(0.0f, xf);
        int ymin = (int)fmaxf(0.0f, yf);
        int xmax = (int)fminf((float)WW, __fadd_rn(xf, wf));
        int ymax = (int)fminf((float)HH, __fadd_rn(yf, hf));
        fix_axis(xmin, xmax, PW, WW);
        fix_axis(ymin, ymax, PH, HH);
        g_rois[(size_t)b * NREG + tid] = make_int4(xmin, ymin, xmax - xmin, ymax - ymin);
        if (write_tail) {
            float* o = out_tail + ((size_t)b * NREG + tid) * 4;
            o[0] = (float)xmin;
            o[1] = (float)ymin;
            o[2] = (float)(xmax - xmin);
            o[3] = (float)(ymax - ymin);
        }
    }
}

__device__ __forceinline__ float4 max4(float4 a, float4 b) {
    float4 r;
    r.x = fmaxf(a.x, b.x);
    r.y = fmaxf(a.y, b.y);
    r.z = fmaxf(a.z, b.z);
    r.w = fmaxf(a.w, b.w);
    return r;
}

// CTA = (region, channel quarter); 4 warps split ALL window rows evenly.
// Bottom row-strip partials accumulate IN SHARED MEMORY (per-warp slice) to
// keep registers <= 64 so 8 CTAs (32 warps) fit per SM.
__global__ void __launch_bounds__(128, 8) pool_kernel(const float* __restrict__ feat,
                                                      float* __restrict__ out) {
    const int reg = blockIdx.x;            // b*NREG + r, 0..1023
    const int q = blockIdx.y;              // channel quarter, 0..3
    const int lane = threadIdx.x & 31;
    const int wrp = threadIdx.x >> 5;      // row-chunk warp, 0..3
    const int b = reg >> 6;
    const int c4 = q * 32 + lane;          // float4 channel group, 0..127

    const int4 g = g_rois[reg];
    const int x = g.x, y = g.y, w = g.z, h = g.w;

    const float4* fm = reinterpret_cast<const float4*>(feat) +
                       (size_t)b * HH * WW * (CC / 4) + c4;
    float4* o = reinterpret_cast<float4*>(out) + (size_t)reg * PH * PW * (CC / 4) + c4;

    auto F = [&](int row, int col) -> float4 {
        return __ldg(&fm[((size_t)row * WW + col) * (CC / 4)]);
    };

    const float4 NI4 = make_float4(NEGINF, NEGINF, NEGINF, NEGINF);

    __shared__ float4 part[4][PW][32];
#pragma unroll
    for (int j = 0; j < PW; j++) part[wrp][j][lane] = NI4;   // own slice, no sync

    float4 c0 = NI4, c1 = NI4;

    // Unified row loop: rows 0..5 produce direct outputs; rows >= 6 accumulate
    // row-strip partials in shared + corner partials in regs.
    for (int r = wrp; r < h; r += 4) {
        const int row = y + r;
        if (r < PH - 1) {
#pragma unroll
            for (int j = 0; j < PW - 1; j++) {
                __stcs(&o[((size_t)r * PW + j) * (CC / 4)], F(row, x + j));
            }
            float4 a0 = F(row, x + 6);
            float4 a1 = NI4, a2 = NI4, a3 = NI4;
            int col = x + 7;
            for (; col + 3 < x + w; col += 4) {
                a0 = max4(a0, F(row, col));
                a1 = max4(a1, F(row, col + 1));
                a2 = max4(a2, F(row, col + 2));
                a3 = max4(a3, F(row, col + 3));
            }
            for (; col < x + w; col++) a0 = max4(a0, F(row, col));
            __stcs(&o[((size_t)r * PW + 6) * (CC / 4)],
                   max4(max4(a0, a1), max4(a2, a3)));
        } else {
#pragma unroll
            for (int j = 0; j < PW - 1; j++) {
                part[wrp][j][lane] = max4(part[wrp][j][lane], F(row, x + j));
            }
            int col = x + 6;
            for (; col + 1 < x + w; col += 2) {
                c0 = max4(c0, F(row, col));
                c1 = max4(c1, F(row, col + 1));
            }
            if (col < x + w) c0 = max4(c0, F(row, col));
        }
    }
    part[wrp][6][lane] = max4(c0, c1);
    __syncthreads();

    for (int j = wrp; j < PW; j += 4) {
        float4 m = max4(max4(part[0][j][lane], part[1][j][lane]),
                        max4(part[2][j][lane], part[3][j][lane]));
        // outputs for pooled row 6: indices 42+j (j=6 -> corner at 48)
        __stcs(&o[(size_t)(42 + j) * (CC / 4)], m);
    }
}

extern "C" void kernel_launch(void* const* d_in, const int* in_sizes, int n_in,
                              void* d_out, int out_size) {
    // metadata order: features (B*H*W*C), roi (B*R*4). Disambiguate by size.
    const float* features = (const float*)d_in[0];
    const float* roi = (const float*)d_in[1];
    if (n_in >= 2 && in_sizes[0] == BB * RR * 4) {
        roi = (const float*)d_in[0];
        features = (const float*)d_in[1];
    }

    const long long pooled_elems = (long long)BB * NREG * PH * PW * CC;  // 25,690,112
    float* out = (float*)d_out;
    int write_tail = (out_size > pooled_elems) ? 1 : 0;
    float* tail = out + pooled_elems;

    nms_clip_kernel<<<BB, 1024>>>(roi, tail, write_tail);
    pool_kernel<<<dim3(BB * NREG, 4, 1), 128>>>(features, out);
}

// round 8
// speedup vs baseline: 4.1209x; 1.0335x over previous
#include <cuda_runtime.h>
#include <cstdint>

#define BB 16
#define HH 64
#define WW 64
#define CC 512
#define RR 256
#define NREG 64
#define PH 7
#define PW 7

#define NEGINF __int_as_float(0xff800000)

// Scratch for clipped ROIs passed from NMS kernel to pooling kernel.
__device__ int4 g_rois[BB * NREG];

__device__ __forceinline__ void fix_axis(int& mn, int& mx, int ps, int fs) {
    int pad = ps - (mx - mn);
    if (pad > 0) {
        if (mn < pad / 2) {
            mn = 0; mx = ps;
        } else if (fs - mx < (1 + pad) / 2) {
            mn = fs - ps; mx = fs;
        } else {
            mn = mn - pad / 2;
            mx = mx + (1 + pad) / 2;
        }
    }
}

// 1024 threads: thread = (roi t, j-segment). Fast divide with exact fallback
// only inside a tiny band around the 0.4 threshold (bit-identical decisions).
// Box coords packed in float4 -> 1 LDS.128 broadcast per inner iteration.
__global__ void __launch_bounds__(1024) nms_clip_kernel(const float* __restrict__ roi,
                                                        float* __restrict__ out_tail,
                                                        int write_tail) {
    const int b = blockIdx.x;       // batch
    const int tid = threadIdx.x;    // 0..1023
    const int t = tid & 255;        // roi index
    const int seg = tid >> 8;       // j-segment, 0..3 (2 words of 32 each)

    __shared__ float4 sbox[RR];          // (x1, y1, x2, y2)
    __shared__ float sar[RR];
    __shared__ unsigned int ov[8][RR];   // transposed: ov[word][roi]
    __shared__ int idx[NREG];

    if (seg == 0) {
        float4 r4 = reinterpret_cast<const float4*>(roi)[(size_t)b * RR + t];
        float x2v = __fadd_rn(r4.x, r4.z);
        float y2v = __fadd_rn(r4.y, r4.w);
        sbox[t] = make_float4(r4.x, r4.y, x2v, y2v);
        sar[t] = __fmul_rn(__fsub_rn(y2v, r4.y), __fsub_rn(x2v, r4.x));
    }
    __syncthreads();

    const float4 mybox = sbox[t];
    const float x1 = mybox.x, y1 = mybox.y, x2 = mybox.z, y2 = mybox.w;
    const float area_t = sar[t];
#pragma unroll
    for (int wi = 0; wi < 2; wi++) {
        const int wd = seg * 2 + wi;
        unsigned int bits = 0;
        for (int k = 0; k < 32; k++) {
            const int j = wd * 32 + k;
            const float4 jb = sbox[j];   // broadcast LDS.128
            float ih = fmaxf(__fsub_rn(fminf(y2, jb.w), fmaxf(y1, jb.y)), 0.0f);
            float iw = fmaxf(__fsub_rn(fminf(x2, jb.z), fmaxf(x1, jb.x)), 0.0f);
            float inter = __fmul_rn(ih, iw);
            float uni = __fsub_rn(__fadd_rn(area_t, sar[j]), inter);
            bool dec = false;
            if (uni > 0.0f) {
                float r = __fdividef(inter, uni);   // ~2 ulp fast path
                if (r > 0.4f + 1e-5f) dec = true;
                else if (r >= 0.4f - 1e-5f)          // ambiguous band: exact
                    dec = __fdiv_rn(inter, uni) > 0.4f;
            }
            if (dec) bits |= (1u << k);
        }
        ov[wd][t] = bits;
    }
    __syncthreads();

    // Block-parallel greedy scan by warp 0: 32 candidates per step.
    if (tid < 32) {
        const int lane = tid;
        unsigned int km[8] = {0, 0, 0, 0, 0, 0, 0, 0};  // kept mask (replicated)
        int cnt = 0;
#pragma unroll
        for (int bb = 0; bb < 8; bb++) {
            const int i = bb * 32 + lane;
            unsigned int s = 0;
#pragma unroll
            for (int wd = 0; wd < 8; wd++) s |= (ov[wd][i] & km[wd]);
            unsigned int candmask = __ballot_sync(0xffffffffu, s == 0u);
            unsigned int myrow = ov[bb][i];  // in-block conflict word for candidate i
            unsigned int kept = 0;
#pragma unroll 8
            for (int k = 0; k < 32; k++) {
                unsigned int rk = __shfl_sync(0xffffffffu, myrow, k);
                if ((candmask >> k) & 1u) {
                    if (!(rk & kept)) kept |= (1u << k);
                }
            }
            if ((kept >> lane) & 1u) {
                int rank = cnt + __popc(kept & ((1u << lane) - 1u));
                if (rank < NREG) idx[rank] = i;
            }
            km[bb] = kept;
            cnt += __popc(kept);
        }
        for (int k = cnt + lane; k < NREG; k += 32) idx[k] = (RR - NREG) + k;
    }
    __syncthreads();

    // Clip the 64 selected ROIs and publish to scratch (+ output tail).
    if (tid < NREG) {
        const float* rr = roi + ((size_t)b * RR + idx[tid]) * 4;
        const float xf = rr[0], yf = rr[1], wf = rr[2], hf = rr[3];
        int xmin = (int)fmaxf(0.0f, xf);
        int ymin = (int)fmaxf(0.0f, yf);
        int xmax = (int)fminf((float)WW, __fadd_rn(xf, wf));
        int ymax = (int)fminf((float)HH, __fadd_rn(yf, hf));
        fix_axis(xmin, xmax, PW, WW);
        fix_axis(ymin, ymax, PH, HH);
        g_rois[(size_t)b * NREG + tid] = make_int4(xmin, ymin, xmax - xmin, ymax - ymin);
        if (write_tail) {
            float* o = out_tail + ((size_t)b * NREG + tid) * 4;
            o[0] = (float)xmin;
            o[1] = (float)ymin;
            o[2] = (float)(xmax - xmin);
            o[3] = (float)(ymax - ymin);
        }
    }
}

__device__ __forceinline__ float4 max4(float4 a, float4 b) {
    float4 r;
    r.x = fmaxf(a.x, b.x);
    r.y = fmaxf(a.y, b.y);
    r.z = fmaxf(a.z, b.z);
    r.w = fmaxf(a.w, b.w);
    return r;
}

// CTA = (q, region) with q the FASTEST grid dimension: the 4 channel-quarter
// CTAs of one region are adjacent block IDs -> co-resident, jointly streaming
// the full 2KB of each pixel (DRAM page locality) and keeping the concurrent
// region window ~4-5 batches (fits L2 easily).
__global__ void __launch_bounds__(128, 8) pool_kernel(const float* __restrict__ feat,
                                                      float* __restrict__ out) {
    const int q = blockIdx.x;              // channel quarter, 0..3 (fast dim)
    const int reg = blockIdx.y;            // b*NREG + r, 0..1023
    const int lane = threadIdx.x & 31;
    const int wrp = threadIdx.x >> 5;      // row-chunk warp, 0..3
    const int b = reg >> 6;
    const int c4 = q * 32 + lane;          // float4 channel group, 0..127

    const int4 g = g_rois[reg];
    const int x = g.x, y = g.y, w = g.z, h = g.w;

    const float4* fm = reinterpret_cast<const float4*>(feat) +
                       (size_t)b * HH * WW * (CC / 4) + c4;
    float4* o = reinterpret_cast<float4*>(out) + (size_t)reg * PH * PW * (CC / 4) + c4;

    auto F = [&](int row, int col) -> float4 {
        return __ldg(&fm[((size_t)row * WW + col) * (CC / 4)]);
    };

    const float4 NI4 = make_float4(NEGINF, NEGINF, NEGINF, NEGINF);

    __shared__ float4 part[4][PW][32];
#pragma unroll
    for (int j = 0; j < PW; j++) part[wrp][j][lane] = NI4;   // own slice, no sync

    float4 c0 = NI4, c1 = NI4;

    // Unified row loop: rows 0..5 produce direct outputs; rows >= 6 accumulate
    // row-strip partials in shared + corner partials in regs.
    for (int r = wrp; r < h; r += 4) {
        const int row = y + r;
        if (r < PH - 1) {
#pragma unroll
            for (int j = 0; j < PW - 1; j++) {
                __stcs(&o[((size_t)r * PW + j) * (CC / 4)], F(row, x + j));
            }
            float4 a0 = F(row, x + 6);
            float4 a1 = NI4, a2 = NI4, a3 = NI4;
            int col = x + 7;
            for (; col + 3 < x + w; col += 4) {
                a0 = max4(a0, F(row, col));
                a1 = max4(a1, F(row, col + 1));
                a2 = max4(a2, F(row, col + 2));
                a3 = max4(a3, F(row, col + 3));
            }
            for (; col < x + w; col++) a0 = max4(a0, F(row, col));
            __stcs(&o[((size_t)r * PW + 6) * (CC / 4)],
                   max4(max4(a0, a1), max4(a2, a3)));
        } else {
#pragma unroll
            for (int j = 0; j < PW - 1; j++) {
                part[wrp][j][lane] = max4(part[wrp][j][lane], F(row, x + j));
            }
            int col = x + 6;
            for (; col + 1 < x + w; col += 2) {
                c0 = max4(c0, F(row, col));
                c1 = max4(c1, F(row, col + 1));
            }
            if (col < x + w) c0 = max4(c0, F(row, col));
        }
    }
    part[wrp][6][lane] = max4(c0, c1);
    __syncthreads();

    for (int j = wrp; j < PW; j += 4) {
        float4 m = max4(max4(part[0][j][lane], part[1][j][lane]),
                        max4(part[2][j][lane], part[3][j][lane]));
        // outputs for pooled row 6: indices 42+j (j=6 -> corner at 48)
        __stcs(&o[(size_t)(42 + j) * (CC / 4)], m);
    }
}

extern "C" void kernel_launch(void* const* d_in, const int* in_sizes, int n_in,
                              void* d_out, int out_size) {
    // metadata order: features (B*H*W*C), roi (B*R*4). Disambiguate by size.
    const float* features = (const float*)d_in[0];
    const float* roi = (const float*)d_in[1];
    if (n_in >= 2 && in_sizes[0] == BB * RR * 4) {
        roi = (const float*)d_in[0];
        features = (const float*)d_in[1];
    }

    const long long pooled_elems = (long long)BB * NREG * PH * PW * CC;  // 25,690,112
    float* out = (float*)d_out;
    int write_tail = (out_size > pooled_elems) ? 1 : 0;
    float* tail = out + pooled_elems;

    nms_clip_kernel<<<BB, 1024>>>(roi, tail, write_tail);
    pool_kernel<<<dim3(4, BB * NREG, 1), 128>>>(features, out);
}

// round 9
// speedup vs baseline: 4.4127x; 1.0708x over previous
#include <cuda_runtime.h>
#include <cstdint>

#define BB 16
#define HH 64
#define WW 64
#define CC 512
#define RR 256
#define NREG 64
#define PH 7
#define PW 7

#define NEGINF __int_as_float(0xff800000)

// Scratch: clipped ROIs (NMS -> pool) and overlap-bit matrix (iou -> scan).
__device__ int4 g_rois[BB * NREG];
__device__ unsigned int g_ov[BB][8][RR];   // [batch][word][roi]

__device__ __forceinline__ void fix_axis(int& mn, int& mx, int ps, int fs) {
    int pad = ps - (mx - mn);
    if (pad > 0) {
        if (mn < pad / 2) {
            mn = 0; mx = ps;
        } else if (fs - mx < (1 + pad) / 2) {
            mn = fs - ps; mx = fs;
        } else {
            mn = mn - pad / 2;
            mx = mx + (1 + pad) / 2;
        }
    }
}

// Kernel A: IoU overlap bits. grid (8 words, 16 batches) x 256 threads.
// Thread t computes word `wd` of roi t's overlap row: 32 IoU evaluations.
// Fast divide with exact fallback only in a tiny band around the threshold
// (bit-identical decisions vs full-precision divide).
__global__ void __launch_bounds__(256) nms_iou_kernel(const float* __restrict__ roi) {
    const int wd = blockIdx.x;      // word, 0..7
    const int b = blockIdx.y;       // batch
    const int t = threadIdx.x;      // roi index

    __shared__ float4 sbox[RR];     // (x1, y1, x2, y2)
    __shared__ float sar[RR];

    float4 r4 = reinterpret_cast<const float4*>(roi)[(size_t)b * RR + t];
    float x2v = __fadd_rn(r4.x, r4.z);
    float y2v = __fadd_rn(r4.y, r4.w);
    sbox[t] = make_float4(r4.x, r4.y, x2v, y2v);
    sar[t] = __fmul_rn(__fsub_rn(y2v, r4.y), __fsub_rn(x2v, r4.x));
    __syncthreads();

    const float4 mybox = sbox[t];
    const float x1 = mybox.x, y1 = mybox.y, x2 = mybox.z, y2 = mybox.w;
    const float area_t = sar[t];

    unsigned int bits = 0;
#pragma unroll 8
    for (int k = 0; k < 32; k++) {
        const int j = wd * 32 + k;
        const float4 jb = sbox[j];   // broadcast LDS.128
        float ih = fmaxf(__fsub_rn(fminf(y2, jb.w), fmaxf(y1, jb.y)), 0.0f);
        float iw = fmaxf(__fsub_rn(fminf(x2, jb.z), fmaxf(x1, jb.x)), 0.0f);
        float inter = __fmul_rn(ih, iw);
        float uni = __fsub_rn(__fadd_rn(area_t, sar[j]), inter);
        bool dec = false;
        if (uni > 0.0f) {
            float r = __fdividef(inter, uni);   // ~2 ulp fast path
            if (r > 0.4f + 1e-5f) dec = true;
            else if (r >= 0.4f - 1e-5f)          // ambiguous band: exact
                dec = __fdiv_rn(inter, uni) > 0.4f;
        }
        if (dec) bits |= (1u << k);
    }
    g_ov[b][wd][t] = bits;
}

// Kernel B: greedy scan + clip. 16 blocks x 256 threads.
__global__ void __launch_bounds__(256) nms_scan_kernel(const float* __restrict__ roi,
                                                       float* __restrict__ out_tail,
                                                       int write_tail) {
    const int b = blockIdx.x;
    const int tid = threadIdx.x;

    __shared__ unsigned int ov[8][RR];
    __shared__ int idx[NREG];

    // Stage overlap matrix into shared (2048 words, 8 per thread).
    {
        const unsigned int* src = &g_ov[b][0][0];
        unsigned int* dst = &ov[0][0];
#pragma unroll
        for (int i = 0; i < 8; i++) dst[tid + i * 256] = src[tid + i * 256];
    }
    __syncthreads();

    // Block-parallel greedy scan by warp 0: 32 candidates per step.
    if (tid < 32) {
        const int lane = tid;
        unsigned int km[8] = {0, 0, 0, 0, 0, 0, 0, 0};  // kept mask (replicated)
        int cnt = 0;
#pragma unroll
        for (int bb = 0; bb < 8; bb++) {
            const int i = bb * 32 + lane;
            unsigned int s = 0;
#pragma unroll
            for (int wd = 0; wd < 8; wd++) s |= (ov[wd][i] & km[wd]);
            unsigned int candmask = __ballot_sync(0xffffffffu, s == 0u);
            unsigned int myrow = ov[bb][i];  // in-block conflict word for candidate i
            unsigned int kept = 0;
#pragma unroll 8
            for (int k = 0; k < 32; k++) {
                unsigned int rk = __shfl_sync(0xffffffffu, myrow, k);
                if ((candmask >> k) & 1u) {
                    if (!(rk & kept)) kept |= (1u << k);
                }
            }
            if ((kept >> lane) & 1u) {
                int rank = cnt + __popc(kept & ((1u << lane) - 1u));
                if (rank < NREG) idx[rank] = i;
            }
            km[bb] = kept;
            cnt += __popc(kept);
        }
        for (int k = cnt + lane; k < NREG; k += 32) idx[k] = (RR - NREG) + k;
    }
    __syncthreads();

    // Clip the 64 selected ROIs and publish to scratch (+ output tail).
    if (tid < NREG) {
        const float* rr = roi + ((size_t)b * RR + idx[tid]) * 4;
        const float xf = rr[0], yf = rr[1], wf = rr[2], hf = rr[3];
        int xmin = (int)fmaxf(0.0f, xf);
        int ymin = (int)fmaxf(0.0f, yf);
        int xmax = (int)fminf((float)WW, __fadd_rn(xf, wf));
        int ymax = (int)fminf((float)HH, __fadd_rn(yf, hf));
        fix_axis(xmin, xmax, PW, WW);
        fix_axis(ymin, ymax, PH, HH);
        g_rois[(size_t)b * NREG + tid] = make_int4(xmin, ymin, xmax - xmin, ymax - ymin);
        if (write_tail) {
            float* o = out_tail + ((size_t)b * NREG + tid) * 4;
            o[0] = (float)xmin;
            o[1] = (float)ymin;
            o[2] = (float)(xmax - xmin);
            o[3] = (float)(ymax - ymin);
        }
    }
}

__device__ __forceinline__ float4 max4(float4 a, float4 b) {
    float4 r;
    r.x = fmaxf(a.x, b.x);
    r.y = fmaxf(a.y, b.y);
    r.z = fmaxf(a.z, b.z);
    r.w = fmaxf(a.w, b.w);
    return r;
}

// CTA = (q, region) with q the fastest grid dimension; 4 warps split all
// window rows; bottom-strip partials accumulate in shared (regs <= 64,
// 8 CTAs/SM). Output stores are streaming (.cs).
__global__ void __launch_bounds__(128, 8) pool_kernel(const float* __restrict__ feat,
                                                      float* __restrict__ out) {
    const int q = blockIdx.x;              // channel quarter, 0..3 (fast dim)
    const int reg = blockIdx.y;            // b*NREG + r, 0..1023
    const int lane = threadIdx.x & 31;
    const int wrp = threadIdx.x >> 5;      // row-chunk warp, 0..3
    const int b = reg >> 6;
    const int c4 = q * 32 + lane;          // float4 channel group, 0..127

    const int4 g = g_rois[reg];
    const int x = g.x, y = g.y, w = g.z, h = g.w;

    const float4* fm = reinterpret_cast<const float4*>(feat) +
                       (size_t)b * HH * WW * (CC / 4) + c4;
    float4* o = reinterpret_cast<float4*>(out) + (size_t)reg * PH * PW * (CC / 4) + c4;

    auto F = [&](int row, int col) -> float4 {
        return __ldg(&fm[((size_t)row * WW + col) * (CC / 4)]);
    };

    const float4 NI4 = make_float4(NEGINF, NEGINF, NEGINF, NEGINF);

    __shared__ float4 part[4][PW][32];
#pragma unroll
    for (int j = 0; j < PW; j++) part[wrp][j][lane] = NI4;   // own slice, no sync

    float4 c0 = NI4, c1 = NI4;

    // Unified row loop: rows 0..5 produce direct outputs; rows >= 6 accumulate
    // row-strip partials in shared + corner partials in regs.
    for (int r = wrp; r < h; r += 4) {
        const int row = y + r;
        if (r < PH - 1) {
#pragma unroll
            for (int j = 0; j < PW - 1; j++) {
                __stcs(&o[((size_t)r * PW + j) * (CC / 4)], F(row, x + j));
            }
            float4 a0 = F(row, x + 6);
            float4 a1 = NI4, a2 = NI4, a3 = NI4;
            int col = x + 7;
            for (; col + 3 < x + w; col += 4) {
                a0 = max4(a0, F(row, col));
                a1 = max4(a1, F(row, col + 1));
                a2 = max4(a2, F(row, col + 2));
                a3 = max4(a3, F(row, col + 3));
            }
            for (; col < x + w; col++) a0 = max4(a0, F(row, col));
            __stcs(&o[((size_t)r * PW + 6) * (CC / 4)],
                   max4(max4(a0, a1), max4(a2, a3)));
        } else {
#pragma unroll
            for (int j = 0; j < PW - 1; j++) {
                part[wrp][j][lane] = max4(part[wrp][j][lane], F(row, x + j));
            }
            int col = x + 6;
            for (; col + 1 < x + w; col += 2) {
                c0 = max4(c0, F(row, col));
                c1 = max4(c1, F(row, col + 1));
            }
            if (col < x + w) c0 = max4(c0, F(row, col));
        }
    }
    part[wrp][6][lane] = max4(c0, c1);
    __syncthreads();

    for (int j = wrp; j < PW; j += 4) {
        float4 m = max4(max4(part[0][j][lane], part[1][j][lane]),
                        max4(part[2][j][lane], part[3][j][lane]));
        // outputs for pooled row 6: indices 42+j (j=6 -> corner at 48)
        __stcs(&o[(size_t)(42 + j) * (CC / 4)], m);
    }
}

extern "C" void kernel_launch(void* const* d_in, const int* in_sizes, int n_in,
                              void* d_out, int out_size) {
    // metadata order: features (B*H*W*C), roi (B*R*4). Disambiguate by size.
    const float* features = (const float*)d_in[0];
    const float* roi = (const float*)d_in[1];
    if (n_in >= 2 && in_sizes[0] == BB * RR * 4) {
        roi = (const float*)d_in[0];
        features = (const float*)d_in[1];
    }

    const long long pooled_elems = (long long)BB * NREG * PH * PW * CC;  // 25,690,112
    float* out = (float*)d_out;
    int write_tail = (out_size > pooled_elems) ? 1 : 0;
    float* tail = out + pooled_elems;

    nms_iou_kernel<<<dim3(8, BB, 1), 256>>>(roi);
    nms_scan_kernel<<<BB, 256>>>(roi, tail, write_tail);
    pool_kernel<<<dim3(4, BB * NREG, 1), 128>>>(features, out);
}